// round 8
// baseline (speedup 1.0000x reference)
#include <cuda_runtime.h>
#include <cstdint>

// Problem constants
#define BATCH      32768
#define NFEAT      128
#define NTREES     4000
#define NINT       63
#define NLEAF      64
#define NCLS       10
#define LR         0.1f

// Tiling: one CTA per SM; 224 samples, 448 threads (2 threads/sample, each
// owning half the stages of every chunk) -> 14 warps.
#define SPC        224
#define TPB        448
#define GRID       ((BATCH + SPC - 1) / SPC)   // 147

#define CHUNK_STAGES 8
#define CHUNK_TREES  (CHUNK_STAGES * NCLS)     // 80 trees per buffer
#define NCHUNK       (NTREES / CHUNK_TREES)    // 50

// Node word (built by prep kernel): (f*448)<<16 | hi16(key(threshold))
// Low 16 bits of the threshold key live in g_thrlo (global, read only on ties).
#define NODEQ_CHUNK  (CHUNK_TREES * NINT)      // 5040 u32
#define NODEQ_BYTES  (NODEQ_CHUNK * 4)         // 20160 (16B multiple)
#define LEAF_CHUNK   (CHUNK_TREES * NLEAF)     // 5120 f32
#define LEAF_BYTES   (LEAF_CHUNK * 4)          // 20480
#define BUF_BYTES    (NODEQ_BYTES + LEAF_BYTES)// 40640

// x tiles: FEATURE-MAJOR u16, xhi[f*SPC + r], xlo likewise.
#define XH_BYTES    (NFEAT * SPC * 2)          // 57344
#define XH_OFF      0
#define XL_OFF      XH_BYTES                   // 57344
#define BUF_OFF(b)  (2 * XH_BYTES + (b) * BUF_BYTES)
#define MBAR_OFF    (2 * XH_BYTES + 2 * BUF_BYTES)   // 195968
#define SMEM_TOTAL  (MBAR_OFF + 16)            // 195984

__device__ __align__(16) uint32_t g_nodesQ[NTREES * NINT];
__device__ uint16_t g_thrlo[NTREES * NINT];

extern __shared__ char smem_raw[];

__device__ __forceinline__ uint32_t fkey(float v) {
    int b = __float_as_int(v);
    return (uint32_t)(b ^ ((b >> 31) | 0x80000000));
}

__device__ __forceinline__ uint32_t s2u(const void* p) {
    uint32_t a;
    asm("{ .reg .u64 t; cvta.to.shared.u64 t, %1; cvt.u32.u64 %0, t; }"
        : "=r"(a) : "l"(p));
    return a;
}

__device__ __forceinline__ void mbar_init(uint32_t bar, uint32_t cnt) {
    asm volatile("mbarrier.init.shared.b64 [%0], %1;" :: "r"(bar), "r"(cnt) : "memory");
}

__device__ __forceinline__ void mbar_expect_tx(uint32_t bar, uint32_t bytes) {
    asm volatile("mbarrier.arrive.expect_tx.shared.b64 _, [%0], %1;"
                 :: "r"(bar), "r"(bytes) : "memory");
}

__device__ __forceinline__ void mbar_wait(uint32_t bar, uint32_t parity) {
    uint32_t done;
    asm volatile(
        "{\n\t.reg .pred p;\n\t"
        "mbarrier.try_wait.parity.acquire.cta.shared::cta.b64 p, [%1], %2;\n\t"
        "selp.b32 %0, 1, 0, p;\n\t}"
        : "=r"(done) : "r"(bar), "r"(parity) : "memory");
    while (!done) {
        asm volatile(
            "{\n\t.reg .pred p;\n\t"
            "mbarrier.try_wait.parity.acquire.cta.shared::cta.b64 p, [%1], %2, 0x989680;\n\t"
            "selp.b32 %0, 1, 0, p;\n\t}"
            : "=r"(done) : "r"(bar), "r"(parity) : "memory");
    }
}

__device__ __forceinline__ void bulk_g2s(uint32_t dst, const void* src,
                                         uint32_t bytes, uint32_t bar) {
    asm volatile(
        "cp.async.bulk.shared::cluster.global.mbarrier::complete_tx::bytes "
        "[%0], [%1], %2, [%3];"
        :: "r"(dst), "l"(src), "r"(bytes), "r"(bar) : "memory");
}

// ---- one-time prep: node word = (f*448)<<16 | keyhi; thrlo stored aside ----
__global__ void prep_nodes_kernel(const int* __restrict__ features,
                                  const float* __restrict__ thresholds)
{
    int i = blockIdx.x * blockDim.x + threadIdx.x;
    if (i >= NTREES * NINT) return;
    uint32_t key  = fkey(thresholds[i]);
    uint32_t foff = (uint32_t)features[i] * (SPC * 2);   // byte offset into u16 tile
    g_nodesQ[i] = (foff << 16) | (key >> 16);
    g_thrlo[i]  = (uint16_t)(key & 0xFFFFu);
}

__global__ void __launch_bounds__(TPB, 1)
gbt_forest_kernel(const float* __restrict__ x,
                  const float* __restrict__ leaf_values,
                  const float* __restrict__ init_out,
                  float*       __restrict__ out)
{
    uint64_t* mbar = reinterpret_cast<uint64_t*>(smem_raw + MBAR_OFF);

    const int tid  = threadIdx.x;
    const int half = tid >= SPC;         // 0: stages 0-3 of chunk, 1: stages 4-7
    const int r    = tid - half * SPC;   // sample slot 0..223
    const int base = blockIdx.x * SPC;

    const uint32_t bar0 = s2u(&mbar[0]);
    const uint32_t bar1 = s2u(&mbar[1]);
    const uint32_t dst0 = s2u(smem_raw + BUF_OFF(0));
    const uint32_t dst1 = s2u(smem_raw + BUF_OFF(1));

    const uint32_t* gN = g_nodesQ;

    // --- init barriers + prefetch chunks 0,1 ---
    if (tid == 0) {
        mbar_init(bar0, 1);
        mbar_init(bar1, 1);
        asm volatile("fence.proxy.async.shared::cta;" ::: "memory");
        mbar_expect_tx(bar0, BUF_BYTES);
        bulk_g2s(dst0,               gN,                        NODEQ_BYTES, bar0);
        bulk_g2s(dst0 + NODEQ_BYTES, leaf_values,               LEAF_BYTES,  bar0);
        mbar_expect_tx(bar1, BUF_BYTES);
        bulk_g2s(dst1,               gN + NODEQ_CHUNK,          NODEQ_BYTES, bar1);
        bulk_g2s(dst1 + NODEQ_BYTES, leaf_values + LEAF_CHUNK,  LEAF_BYTES,  bar1);
    }

    // --- stage x: compute monotone keys, store hi/lo u16 tiles transposed ---
    {
        uint16_t* xh = reinterpret_cast<uint16_t*>(smem_raw + XH_OFF);
        uint16_t* xl = reinterpret_cast<uint16_t*>(smem_raw + XL_OFF);
        const int gr = min(base + r, BATCH - 1);
        const float4* xg = reinterpret_cast<const float4*>(x + (size_t)gr * NFEAT)
                         + half * 16;               // half 0: f 0-63, half 1: f 64-127
        #pragma unroll
        for (int fq = 0; fq < 16; fq++) {
            float4 v = xg[fq];
            const int f = half * 64 + fq * 4;
            uint32_t k0 = fkey(v.x), k1 = fkey(v.y), k2 = fkey(v.z), k3 = fkey(v.w);
            xh[(f + 0) * SPC + r] = (uint16_t)(k0 >> 16);
            xh[(f + 1) * SPC + r] = (uint16_t)(k1 >> 16);
            xh[(f + 2) * SPC + r] = (uint16_t)(k2 >> 16);
            xh[(f + 3) * SPC + r] = (uint16_t)(k3 >> 16);
            xl[(f + 0) * SPC + r] = (uint16_t)k0;
            xl[(f + 1) * SPC + r] = (uint16_t)k1;
            xl[(f + 2) * SPC + r] = (uint16_t)k2;
            xl[(f + 3) * SPC + r] = (uint16_t)k3;
        }
    }
    __syncthreads();

    float acc[NCLS];
    #pragma unroll
    for (int k = 0; k < NCLS; k++) acc[k] = 0.0f;

    const char* xhB = smem_raw + XH_OFF + r * 2;   // + foff -> this sample's keyhi
    const char* xlB = smem_raw + XL_OFF + r * 2;
    const int sgBase = half * 4;

    uint32_t barCur = bar0, barNxt = bar1;
    uint32_t dstCur = dst0, dstNxt = dst1;
    const char* pCur = smem_raw + BUF_OFF(0);
    const char* pNxt = smem_raw + BUF_OFF(1);
    int phCur = 0, phNxt = 0;

    for (int c = 0; c < NCHUNK; c++) {
        mbar_wait(barCur, phCur);
        phCur ^= 1;

        const uint32_t* nodeB = reinterpret_cast<const uint32_t*>(pCur);
        const float*    leafB = reinterpret_cast<const float*>(pCur + NODEQ_BYTES);
        const uint16_t* gTL   = g_thrlo + (size_t)c * NODEQ_CHUNK;  // tie path only

        #pragma unroll
        for (int s = 0; s < 4; s++) {
            const int sg = sgBase + s;
            #pragma unroll
            for (int k = 0; k < NCLS; k++) {
                const int j = sg * NCLS + k;
                const uint32_t* nt = nodeB + j * NINT;
                const uint16_t* tl = gTL   + j * NINT;
                int idx = 0;
                #pragma unroll
                for (int l = 0; l < 5; l++) {
                    uint32_t nw = nt[idx];
                    uint32_t XH = *reinterpret_cast<const uint16_t*>(xhB + (nw >> 16));
                    uint32_t TH = nw & 0xFFFFu;
                    int gt;
                    if (__builtin_expect(XH == TH, 0)) {     // rare exact-tie path
                        uint32_t XL = *reinterpret_cast<const uint16_t*>(xlB + (nw >> 16));
                        gt = (int)(XL > (uint32_t)tl[idx]);  // LDG, L2-hot
                    } else {
                        gt = (int)(XH > TH);
                    }
                    idx = 2 * idx + 1 + gt;
                }
                // Level 5: leaf pair fetched independently of the compare (ILP)
                int m = idx - 31;                            // 0..31
                float2 lp = *reinterpret_cast<const float2*>(leafB + j * NLEAF + 2 * m);
                uint32_t nw = nt[idx];
                uint32_t XH = *reinterpret_cast<const uint16_t*>(xhB + (nw >> 16));
                uint32_t TH = nw & 0xFFFFu;
                int gt;
                if (__builtin_expect(XH == TH, 0)) {
                    uint32_t XL = *reinterpret_cast<const uint16_t*>(xlB + (nw >> 16));
                    gt = (int)(XL > (uint32_t)tl[idx]);
                } else {
                    gt = (int)(XH > TH);
                }
                acc[k] += gt ? lp.y : lp.x;
            }
        }

        __syncthreads();   // all warps done with this buffer before overwrite
        if (c + 2 < NCHUNK && tid == 0) {
            const int nc = c + 2;
            mbar_expect_tx(barCur, BUF_BYTES);
            bulk_g2s(dstCur,               gN + (size_t)nc * NODEQ_CHUNK, NODEQ_BYTES, barCur);
            bulk_g2s(dstCur + NODEQ_BYTES, leaf_values + (size_t)nc * LEAF_CHUNK, LEAF_BYTES, barCur);
        }

        uint32_t tb = barCur; barCur = barNxt; barNxt = tb;
        uint32_t td = dstCur; dstCur = dstNxt; dstNxt = td;
        const char* tp = pCur; pCur = pNxt; pNxt = tp;
        int tph = phCur; phCur = phNxt; phNxt = tph;
    }

    // --- cross-half reduction through smem (reuse x tile region) ---
    float* red = reinterpret_cast<float*>(smem_raw);
    if (half == 1) {
        #pragma unroll
        for (int k = 0; k < NCLS; k++) red[r * NCLS + k] = acc[k];
    }
    __syncthreads();

    if (half == 0 && base + r < BATCH) {
        const int sample = base + r;
        #pragma unroll
        for (int k = 0; k < NCLS; k++) {
            out[(size_t)sample * NCLS + k] =
                __ldg(init_out + k) + LR * (acc[k] + red[r * NCLS + k]);
        }
    }
}

extern "C" void kernel_launch(void* const* d_in, const int* in_sizes, int n_in,
                              void* d_out, int out_size)
{
    (void)in_sizes; (void)n_in; (void)out_size;

    const float* x           = (const float*)d_in[0];
    const int*   features    = (const int*)  d_in[1];
    const float* thresholds  = (const float*)d_in[2];
    const float* leaf_values = (const float*)d_in[3];
    const float* init_out    = (const float*)d_in[4];
    float*       out         = (float*)d_out;

    static bool attr_set = false;
    if (!attr_set) {
        cudaFuncSetAttribute(gbt_forest_kernel,
                             cudaFuncAttributeMaxDynamicSharedMemorySize,
                             SMEM_TOTAL);
        attr_set = true;
    }

    prep_nodes_kernel<<<(NTREES * NINT + 255) / 256, 256>>>(features, thresholds);
    gbt_forest_kernel<<<GRID, TPB, SMEM_TOTAL>>>(x, leaf_values, init_out, out);
}

// round 9
// speedup vs baseline: 1.3792x; 1.3792x over previous
#include <cuda_runtime.h>
#include <cstdint>

// Problem constants
#define BATCH      32768
#define NFEAT      128
#define NTREES     4000
#define NINT       63
#define NLEAF      64
#define NCLS       10
#define LR         0.1f

// Main-kernel tiling: one CTA per SM; 224 samples, 448 threads (2 threads per
// sample, each owning half the stages of every chunk) -> 14 warps.
#define SPC        224
#define TPB        448
#define GRID       ((BATCH + SPC - 1) / SPC)   // 147

#define CHUNK_STAGES 8
#define CHUNK_TREES  (CHUNK_STAGES * NCLS)     // 80 trees per buffer
#define NCHUNK       (NTREES / CHUNK_TREES)    // 50

// Node word: (f << 16) | j, where j = rank code of threshold within feature f.
#define NODE_CHUNK   (CHUNK_TREES * NINT)      // 5040 u32
#define NODE_BYTES   (NODE_CHUNK * 4)          // 20160
#define LEAF_CHUNK   (CHUNK_TREES * NLEAF)     // 5120 f32
#define LEAF_BYTES   (LEAF_CHUNK * 4)          // 20480
#define BUF_BYTES    (NODE_BYTES + LEAF_BYTES) // 40640

// x-code tile: FEATURE-MAJOR u32, xs[f*SPC + r]; 224 ≡ 0 (mod 32) -> bank = r.
#define XS_BYTES    (NFEAT * SPC * 4)          // 114688
#define BUF_OFF(b)  (XS_BYTES + (b) * BUF_BYTES)
#define MBAR_OFF    (XS_BYTES + 2 * BUF_BYTES) // 195968
#define SMEM_TOTAL  (MBAR_OFF + 16)            // 195984

#define SORTN 4096                              // per-feature sort size (max m ~2100)
#define PREP_SMEM (SORTN * 8 + SORTN * 4)       // 49152

// Device-global scratch (allowed; rebuilt deterministically every launch)
__device__ __align__(16) uint32_t g_nodesQ[NTREES * NINT];  // (f<<16)|j
__device__ uint16_t g_xcode[(size_t)NFEAT * BATCH];          // per (f,sample) rank code
__device__ int      g_fcount[NFEAT];
__device__ int      g_fbase[NFEAT + 1];
__device__ int      g_fcur[NFEAT];
__device__ uint32_t g_tkey[NTREES * NINT];
__device__ int      g_tid_[NTREES * NINT];

extern __shared__ char smem_raw[];

// Order-preserving float -> u32 key (monotone; -0 canonicalized by caller).
__device__ __forceinline__ uint32_t fkey(float v) {
    int b = __float_as_int(v);
    return (uint32_t)(b ^ ((b >> 31) | 0x80000000));
}

__device__ __forceinline__ uint32_t s2u(const void* p) {
    uint32_t a;
    asm("{ .reg .u64 t; cvta.to.shared.u64 t, %1; cvt.u32.u64 %0, t; }"
        : "=r"(a) : "l"(p));
    return a;
}

__device__ __forceinline__ void mbar_init(uint32_t bar, uint32_t cnt) {
    asm volatile("mbarrier.init.shared.b64 [%0], %1;" :: "r"(bar), "r"(cnt) : "memory");
}

__device__ __forceinline__ void mbar_expect_tx(uint32_t bar, uint32_t bytes) {
    asm volatile("mbarrier.arrive.expect_tx.shared.b64 _, [%0], %1;"
                 :: "r"(bar), "r"(bytes) : "memory");
}

__device__ __forceinline__ void mbar_wait(uint32_t bar, uint32_t parity) {
    uint32_t done;
    asm volatile(
        "{\n\t.reg .pred p;\n\t"
        "mbarrier.try_wait.parity.acquire.cta.shared::cta.b64 p, [%1], %2;\n\t"
        "selp.b32 %0, 1, 0, p;\n\t}"
        : "=r"(done) : "r"(bar), "r"(parity) : "memory");
    while (!done) {
        asm volatile(
            "{\n\t.reg .pred p;\n\t"
            "mbarrier.try_wait.parity.acquire.cta.shared::cta.b64 p, [%1], %2, 0x989680;\n\t"
            "selp.b32 %0, 1, 0, p;\n\t}"
            : "=r"(done) : "r"(bar), "r"(parity) : "memory");
    }
}

__device__ __forceinline__ void bulk_g2s(uint32_t dst, const void* src,
                                         uint32_t bytes, uint32_t bar) {
    asm volatile(
        "cp.async.bulk.shared::cluster.global.mbarrier::complete_tx::bytes "
        "[%0], [%1], %2, [%3];"
        :: "r"(dst), "l"(src), "r"(bytes), "r"(bar) : "memory");
}

// ============================ prep kernels ============================

__global__ void prep_zero_kernel() {
    if (threadIdx.x < NFEAT) g_fcount[threadIdx.x] = 0;
}

__global__ void prep_count_kernel(const int* __restrict__ features) {
    int i = blockIdx.x * blockDim.x + threadIdx.x;
    if (i < NTREES * NINT) atomicAdd(&g_fcount[features[i]], 1);
}

__global__ void prep_prefix_kernel() {
    if (threadIdx.x == 0) {
        int acc = 0;
        for (int f = 0; f < NFEAT; f++) {
            g_fbase[f] = acc; g_fcur[f] = acc; acc += g_fcount[f];
        }
        g_fbase[NFEAT] = acc;
    }
}

__global__ void prep_scatter_kernel(const int* __restrict__ features,
                                    const float* __restrict__ thresholds) {
    int i = blockIdx.x * blockDim.x + threadIdx.x;
    if (i < NTREES * NINT) {
        int f = features[i];
        int p = atomicAdd(&g_fcur[f], 1);
        float t = thresholds[i] + 0.0f;        // canonicalize -0
        g_tkey[p] = fkey(t);
        g_tid_[p] = i;
    }
}

// Per-feature: bitonic sort thresholds, emit node codes j = #{t <= thr} and
// sample codes c = #{t < x}. x > thr <=> c >= j (exact, duplicates included).
__global__ void __launch_bounds__(1024, 1)
prep_feature_kernel(const float* __restrict__ x)
{
    extern __shared__ char sm4[];
    uint64_t* spair = reinterpret_cast<uint64_t*>(sm4);             // SORTN
    uint32_t* skey  = reinterpret_cast<uint32_t*>(sm4 + SORTN * 8); // SORTN

    const int f   = blockIdx.x;
    const int tid = threadIdx.x;
    const int fb  = g_fbase[f];
    const int m   = g_fbase[f + 1] - fb;

    for (int p = tid; p < SORTN; p += 1024)
        spair[p] = (p < m)
            ? (((uint64_t)g_tkey[fb + p] << 32) | (uint32_t)g_tid_[fb + p])
            : 0xFFFFFFFFFFFFFFFFull;
    __syncthreads();

    // Bitonic sort ascending by packed (key, id)
    for (int k = 2; k <= SORTN; k <<= 1) {
        for (int jj = k >> 1; jj > 0; jj >>= 1) {
            for (int i = tid; i < SORTN; i += 1024) {
                int p = i ^ jj;
                if (p > i) {
                    uint64_t a = spair[i], b = spair[p];
                    bool up = ((i & k) == 0);
                    if ((a > b) == up) { spair[i] = b; spair[p] = a; }
                }
            }
            __syncthreads();
        }
    }

    for (int p = tid; p < SORTN; p += 1024)
        skey[p] = (uint32_t)(spair[p] >> 32);
    __syncthreads();

    // Node codes: j = upper_bound(key) = #{t <= thr}
    for (int p = tid; p < m; p += 1024) {
        uint32_t key = skey[p];
        uint32_t id  = (uint32_t)(spair[p] & 0xFFFFFFFFull);
        int pos = 0;
        #pragma unroll
        for (int w = SORTN >> 1; w >= 1; w >>= 1)
            if (skey[pos + w - 1] <= key) pos += w;
        g_nodesQ[id] = ((uint32_t)f << 16) | (uint32_t)pos;
    }

    // Sample codes: c = lower_bound(key(x)) = #{t < x}
    for (int s = tid; s < BATCH; s += 1024) {
        float v = x[(size_t)s * NFEAT + f] + 0.0f;
        uint32_t key = fkey(v);
        int pos = 0;
        #pragma unroll
        for (int w = SORTN >> 1; w >= 1; w >>= 1)
            if (skey[pos + w - 1] < key) pos += w;
        g_xcode[(size_t)f * BATCH + s] = (uint16_t)pos;
    }
}

// ============================ main kernel ============================

__global__ void __launch_bounds__(TPB, 1)
gbt_forest_kernel(const float* __restrict__ leaf_values,
                  const float* __restrict__ init_out,
                  float*       __restrict__ out)
{
    uint32_t* xsw = reinterpret_cast<uint32_t*>(smem_raw);
    uint64_t* mbar = reinterpret_cast<uint64_t*>(smem_raw + MBAR_OFF);

    const int tid  = threadIdx.x;
    const int half = tid >= SPC;          // 0: stages 0-3, 1: stages 4-7
    const int r    = tid - half * SPC;    // sample slot 0..223
    const int base = blockIdx.x * SPC;

    const uint32_t bar0 = s2u(&mbar[0]);
    const uint32_t bar1 = s2u(&mbar[1]);
    const uint32_t dst0 = s2u(smem_raw + BUF_OFF(0));
    const uint32_t dst1 = s2u(smem_raw + BUF_OFF(1));

    const uint32_t* gN = g_nodesQ;

    if (tid == 0) {
        mbar_init(bar0, 1);
        mbar_init(bar1, 1);
        asm volatile("fence.proxy.async.shared::cta;" ::: "memory");
        mbar_expect_tx(bar0, BUF_BYTES);
        bulk_g2s(dst0,              gN,                       NODE_BYTES, bar0);
        bulk_g2s(dst0 + NODE_BYTES, leaf_values,              LEAF_BYTES, bar0);
        mbar_expect_tx(bar1, BUF_BYTES);
        bulk_g2s(dst1,              gN + NODE_CHUNK,          NODE_BYTES, bar1);
        bulk_g2s(dst1 + NODE_BYTES, leaf_values + LEAF_CHUNK, LEAF_BYTES, bar1);
    }

    // Stage x-code tile (u16 global -> u32 smem, feature-major, conflict-free)
    for (int ii = tid; ii < NFEAT * SPC; ii += TPB) {
        int f  = ii / SPC;
        int rr = ii - f * SPC;
        int gs = min(base + rr, BATCH - 1);
        xsw[f * SPC + rr] = g_xcode[(size_t)f * BATCH + gs];
    }
    __syncthreads();

    float acc[NCLS];
    #pragma unroll
    for (int k = 0; k < NCLS; k++) acc[k] = 0.0f;

    const uint32_t* xcol = xsw + r;
    const int sgBase = half * 4;

    uint32_t barCur = bar0, barNxt = bar1;
    uint32_t dstCur = dst0, dstNxt = dst1;
    const char* pCur = smem_raw + BUF_OFF(0);
    const char* pNxt = smem_raw + BUF_OFF(1);
    int phCur = 0, phNxt = 0;

    for (int c = 0; c < NCHUNK; c++) {
        mbar_wait(barCur, phCur);
        phCur ^= 1;

        const uint32_t* nodeB = reinterpret_cast<const uint32_t*>(pCur);
        const float*    leafB = reinterpret_cast<const float*>(pCur + NODE_BYTES);

        #pragma unroll
        for (int s = 0; s < 4; s++) {
            const int sg = sgBase + s;
            #pragma unroll
            for (int k = 0; k < NCLS; k++) {
                const int j = sg * NCLS + k;
                const uint32_t* nt = nodeB + j * NINT;
                uint32_t idx = 0;
                #pragma unroll
                for (int l = 0; l < 5; l++) {
                    uint32_t nw = nt[idx];                 // 1 wf
                    uint32_t cd = xcol[(nw >> 16) * SPC];  // 1 wf, bank = lane
                    idx = 2 * idx + 1 + (cd >= (nw & 0xFFFFu));   // branchless
                }
                int mq = (int)idx - 31;
                float2 lp = *reinterpret_cast<const float2*>(leafB + j * NLEAF + 2 * mq);
                uint32_t nw = nt[idx];
                uint32_t cd = xcol[(nw >> 16) * SPC];
                acc[k] += (cd >= (nw & 0xFFFFu)) ? lp.y : lp.x;
            }
        }

        __syncthreads();   // all warps done with this buffer before overwrite
        if (c + 2 < NCHUNK && tid == 0) {
            const int nc = c + 2;
            mbar_expect_tx(barCur, BUF_BYTES);
            bulk_g2s(dstCur,              gN + (size_t)nc * NODE_CHUNK, NODE_BYTES, barCur);
            bulk_g2s(dstCur + NODE_BYTES, leaf_values + (size_t)nc * LEAF_CHUNK,
                     LEAF_BYTES, barCur);
        }

        uint32_t tb = barCur; barCur = barNxt; barNxt = tb;
        uint32_t td = dstCur; dstCur = dstNxt; dstNxt = td;
        const char* tp = pCur; pCur = pNxt; pNxt = tp;
        int tph = phCur; phCur = phNxt; phNxt = tph;
    }

    // Cross-half reduction (reuse x tile region; last loop iter ended in sync)
    float* red = reinterpret_cast<float*>(smem_raw);
    if (half == 1) {
        #pragma unroll
        for (int k = 0; k < NCLS; k++) red[r * NCLS + k] = acc[k];
    }
    __syncthreads();

    if (half == 0 && base + r < BATCH) {
        const int sample = base + r;
        #pragma unroll
        for (int k = 0; k < NCLS; k++) {
            out[(size_t)sample * NCLS + k] =
                __ldg(init_out + k) + LR * (acc[k] + red[r * NCLS + k]);
        }
    }
}

extern "C" void kernel_launch(void* const* d_in, const int* in_sizes, int n_in,
                              void* d_out, int out_size)
{
    (void)in_sizes; (void)n_in; (void)out_size;

    const float* x           = (const float*)d_in[0];
    const int*   features    = (const int*)  d_in[1];
    const float* thresholds  = (const float*)d_in[2];
    const float* leaf_values = (const float*)d_in[3];
    const float* init_out    = (const float*)d_in[4];
    float*       out         = (float*)d_out;

    static bool attr_set = false;
    if (!attr_set) {
        cudaFuncSetAttribute(gbt_forest_kernel,
                             cudaFuncAttributeMaxDynamicSharedMemorySize, SMEM_TOTAL);
        cudaFuncSetAttribute(prep_feature_kernel,
                             cudaFuncAttributeMaxDynamicSharedMemorySize, PREP_SMEM);
        attr_set = true;
    }

    const int NELEM = NTREES * NINT;
    prep_zero_kernel<<<1, NFEAT>>>();
    prep_count_kernel<<<(NELEM + 255) / 256, 256>>>(features);
    prep_prefix_kernel<<<1, 32>>>();
    prep_scatter_kernel<<<(NELEM + 255) / 256, 256>>>(features, thresholds);
    prep_feature_kernel<<<NFEAT, 1024, PREP_SMEM>>>(x);
    gbt_forest_kernel<<<GRID, TPB, SMEM_TOTAL>>>(leaf_values, init_out, out);
}